// round 3
// baseline (speedup 1.0000x reference)
#include <cuda_runtime.h>

// Problem constants (shapes fixed by the dataset)
#define B 16
#define F 256
#define T 8192
#define KKEEP 204                 // k = int(256 * (1 - 0.2))

#define N1 (B * F * T)            // 33,554,432 floats per output tensor
#define N4_MASKED (N1 / 4)        // 8,388,608 float4 (masked_x half)

// Fat-block partition:
//   masked region:    1024 blocks x 8192 float4  (4 (b,f) rows per block)
//   broadcast region:  512 blocks x 16384 float4 (1/32 of one batch each)
#define MASKED_BLOCKS 1024
#define MB_F4 8192
#define BCAST_BLOCKS 512
#define BB_F4 16384

// ---------------------------------------------------------------------------
// One fused kernel. Every block first recomputes the 256-wide binary mask row
// for its (uniform) batch b in shared memory (cheap at this block granularity),
// then streams its chunk of the output.
//
// kept(f) <=> #{j : x2[j] > x2[f]} < KKEEP   (tie-correct vs top_k kth value)
// binary  = kept && (x2 > 0)                 (probs > 0.5 <=> wta > 0)
// ---------------------------------------------------------------------------
__global__ void fused_kernel(const float* __restrict__ w_mask,
                             const float* __restrict__ noise,
                             const float4* __restrict__ x,
                             float4* __restrict__ out) {
    __shared__ float s[F];
    __shared__ float mask_s[F];
    const int tid = threadIdx.x;                    // 256 threads
    const bool is_masked = (blockIdx.x < MASKED_BLOCKS);

    int baseV;   // first float4 index of this block in the linear output space
    int b;       // batch (uniform within block by construction)
    if (is_masked) {
        baseV = blockIdx.x * MB_F4;
        b = baseV >> 19;                            // F*T/4 = 524288 f4/batch
    } else {
        const int w0 = (blockIdx.x - MASKED_BLOCKS) * BB_F4;
        b = w0 >> 19;                               // T*F/4 = 524288 f4/batch
        baseV = N4_MASKED + w0;
    }

    // --- mask row for batch b (per-block recompute, overlapped/cheap) ---
    {
        const float w  = w_mask[tid];
        const float sg = 1.0f / (1.0f + __expf(-w));
        const float x2 = sg + 0.05f * noise[b * F + tid];
        s[tid] = x2;
        __syncthreads();
        int gt = 0;
#pragma unroll 16
        for (int j = 0; j < F; ++j)
            gt += (s[j] > x2) ? 1 : 0;              // uniform-addr LDS: N=1
        mask_s[tid] = (gt < KKEEP && x2 > 0.0f) ? 1.0f : 0.0f;
        __syncthreads();
    }

    if (is_masked) {
        // masked_x[b,0,f,t] = mask[b,f] * x[b,0,f,t]
        // 32 iterations of 256 coalesced float4; mask uniform per iteration:
        //   row(v) = baseR + it/8   (exact: tid<256, 2048 f4 per row)
        const int baseR = baseV >> 11;
#pragma unroll
        for (int it = 0; it < 32; it += 4) {
            float4 xv[4];
#pragma unroll
            for (int k = 0; k < 4; ++k)             // front-batch loads (MLP=4)
                xv[k] = __ldcs(&x[baseV + (it + k) * 256 + tid]);
#pragma unroll
            for (int k = 0; k < 4; ++k) {
                const float m = mask_s[(baseR + ((it + k) >> 3)) & (F - 1)];
                xv[k].x *= m; xv[k].y *= m; xv[k].z *= m; xv[k].w *= m;
                __stcs(&out[baseV + (it + k) * 256 + tid], xv[k]);
            }
        }
    } else {
        // binary_mask[b,0,t,f] = mask[b,f]  (write-only broadcast)
        // f4 lane = (w0 + it*256 + tid) & 63 = tid & 63  (w0, it*256 ≡ 0 mod 64)
        const float4 m4 = ((const float4*)mask_s)[tid & 63];
#pragma unroll 8
        for (int it = 0; it < 64; ++it)
            __stcs(&out[baseV + it * 256 + tid], m4);
    }
}

extern "C" void kernel_launch(void* const* d_in, const int* in_sizes, int n_in,
                              void* d_out, int out_size) {
    const float* x      = (const float*)d_in[0];   // (16,1,256,8192) f32
    const float* w_mask = (const float*)d_in[1];   // (1,1,1,256)     f32
    const float* noise  = (const float*)d_in[2];   // (16,1,1,256)    f32
    float* out = (float*)d_out;

    // Launch broadcast blocks only if the output holds both tensors.
    const bool has_bcast = ((long long)out_size >= 2LL * N1);
    const int blocks = MASKED_BLOCKS + (has_bcast ? BCAST_BLOCKS : 0);

    fused_kernel<<<blocks, 256>>>(w_mask, noise,
                                  (const float4*)x, (float4*)out);
}

// round 5
// speedup vs baseline: 1.1121x; 1.1121x over previous
#include <cuda_runtime.h>

// Problem constants (shapes fixed by the dataset)
#define B 16
#define F 256
#define T 8192
#define KKEEP 204                 // k = int(256 * (1 - 0.2))

#define N1 (B * F * T)            // 33,554,432 floats per output tensor
#define N4_MASKED (N1 / 4)        // 8,388,608 float4 (masked_x half)

// Block partition (single kernel):
//   masked region:   8192 fine blocks x 1024 float4  (half a (b,f) row each)
//   broadcast region:1024 blocks x 8192 float4       (1/64 of one batch each)
#define MASKED_BLOCKS 8192
#define MB_F4 1024
#define BCAST_BLOCKS 1024
#define BB_F4 8192

// kept(f) <=> #{j : x2[j] > x2[f]} < KKEEP   (tie-correct vs top_k kth value)
// binary  = kept && (x2 > 0)                 (probs > 0.5 <=> wta > 0)
__global__ void fused_kernel(const float* __restrict__ w_mask,
                             const float* __restrict__ noise,
                             const float4* __restrict__ x,
                             float4* __restrict__ out) {
    // All shared state at kernel scope, 16B-aligned (mask_s is read as float4;
    // LDS.128 from a non-16B-aligned address is a HW trap).
    __shared__ __align__(16) float s[F];
    __shared__ __align__(16) float mask_s[F];
    __shared__ int cnt[8];
    __shared__ float m_sh;

    const int tid = threadIdx.x;                    // 256 threads

    if (blockIdx.x < MASKED_BLOCKS) {
        // ---- masked_x fine block: needs exactly ONE mask value ----
        const int baseV = blockIdx.x * MB_F4;       // first float4 index
        const int b  = baseV >> 19;                 // F*T/4 f4 per batch
        const int f0 = (baseV >> 11) & (F - 1);     // the block's feature row

        // Hoist stream loads ABOVE the mask math so DRAM traffic starts
        // immediately (mask is only needed at store time).
        float4 xv[4];
#pragma unroll
        for (int k = 0; k < 4; ++k)
            xv[k] = __ldcs(&x[baseV + k * 256 + tid]);

        // per-thread x2, then ballot-count against x2[f0]
        const float w  = w_mask[tid];
        const float sg = 1.0f / (1.0f + __expf(-w));
        const float x2 = sg + 0.05f * noise[b * F + tid];
        s[tid] = x2;
        __syncthreads();
        const float x2f = s[f0];
        const unsigned bal = __ballot_sync(0xffffffffu, x2 > x2f);
        if ((tid & 31) == 0) cnt[tid >> 5] = __popc(bal);
        __syncthreads();
        if (tid == 0) {
            int g = 0;
#pragma unroll
            for (int i = 0; i < 8; ++i) g += cnt[i];
            m_sh = (g < KKEEP && x2f > 0.0f) ? 1.0f : 0.0f;
        }
        __syncthreads();
        const float m = m_sh;

#pragma unroll
        for (int k = 0; k < 4; ++k) {
            xv[k].x *= m; xv[k].y *= m; xv[k].z *= m; xv[k].w *= m;
            __stcs(&out[baseV + k * 256 + tid], xv[k]);
        }
    } else {
        // ---- binary_mask block: needs the FULL mask row (write-only) ----
        const int w0 = (blockIdx.x - MASKED_BLOCKS) * BB_F4;
        const int b  = w0 >> 19;                    // T*F/4 f4 per batch
        const int baseV = N4_MASKED + w0;

        const float w  = w_mask[tid];
        const float sg = 1.0f / (1.0f + __expf(-w));
        const float x2 = sg + 0.05f * noise[b * F + tid];
        s[tid] = x2;
        __syncthreads();
        int gt = 0;
#pragma unroll 16
        for (int j = 0; j < F; ++j)
            gt += (s[j] > x2) ? 1 : 0;              // uniform-addr LDS: N=1
        mask_s[tid] = (gt < KKEEP && x2 > 0.0f) ? 1.0f : 0.0f;
        __syncthreads();

        // f4 lane = (w0 + it*256 + tid) & 63 = tid & 63
        const float4 m4 = ((const float4*)mask_s)[tid & 63];
#pragma unroll 8
        for (int it = 0; it < 32; ++it)
            __stcs(&out[baseV + it * 256 + tid], m4);
    }
}

extern "C" void kernel_launch(void* const* d_in, const int* in_sizes, int n_in,
                              void* d_out, int out_size) {
    const float* x      = (const float*)d_in[0];   // (16,1,256,8192) f32
    const float* w_mask = (const float*)d_in[1];   // (1,1,1,256)     f32
    const float* noise  = (const float*)d_in[2];   // (16,1,1,256)    f32
    float* out = (float*)d_out;

    const bool has_bcast = ((long long)out_size >= 2LL * N1);
    const int blocks = MASKED_BLOCKS + (has_bcast ? BCAST_BLOCKS : 0);

    fused_kernel<<<blocks, 256>>>(w_mask, noise,
                                  (const float4*)x, (float4*)out);
}